// round 1
// baseline (speedup 1.0000x reference)
#include <cuda_runtime.h>

// cos(pi*t/16) constants
#define CC1 0.98078528040323044913f
#define CC2 0.92387953251128675613f
#define CC3 0.83146961230254523708f
#define CC4 0.70710678118654752440f
#define CC5 0.55557023301960222474f
#define CC6 0.38268343236508977173f
#define CC7 0.19509032201612826785f

// One thread = one 8x8 spatial tile, all 3 channels.
// Pipeline per tile: load RGB rows -> YUV -> A = D @ X (only kept rows)
// -> B = A @ D^T (only kept cols, per-row prefix) -> C = B @ ID^T (in place over A)
// -> out = ID @ C -> YUV2RGB -> store.
__global__ void __launch_bounds__(128)
jpeg_fused_kernel(const float* __restrict__ in, float* __restrict__ out, int ntiles)
{
    const int g = blockIdx.x * blockDim.x + threadIdx.x;
    if (g >= ntiles) return;

    // D[k][n] = cos(pi/8 * (n+0.5) * k). Local const + full unroll => immediates.
    const float DCTL[8][8] = {
        { 1.f,  1.f,  1.f,  1.f,  1.f,  1.f,  1.f,  1.f},
        { CC1,  CC3,  CC5,  CC7, -CC7, -CC5, -CC3, -CC1},
        { CC2,  CC6, -CC6, -CC2, -CC2, -CC6,  CC6,  CC2},
        { CC3, -CC7, -CC1, -CC5,  CC5,  CC1,  CC7, -CC3},
        { CC4, -CC4, -CC4,  CC4,  CC4, -CC4, -CC4,  CC4},
        { CC5, -CC1,  CC7,  CC3, -CC3, -CC7,  CC1, -CC5},
        { CC6, -CC2,  CC2, -CC6, -CC6,  CC2, -CC2,  CC6},
        { CC7, -CC5,  CC3, -CC1,  CC1, -CC3,  CC5, -CC7}
    };
    // zigzag keep masks are per-row prefixes:
    const int CNTY[7] = {6,5,4,4,3,2,1}; // Y: 25 coeffs, rows 0..6
    const int CNTC[3] = {4,3,2};         // U,V: 9 coeffs, rows 0..2

    const int W = 512;
    const int S = 512 * 512;

    const int b  = g >> 12;        // tiles per image = 64*64 = 4096
    const int t  = g & 4095;
    const int ty = t >> 6;
    const int tx = t & 63;

    const size_t base = (size_t)b * (3 * S) + (size_t)(ty * 8) * W + (size_t)(tx * 8);
    const float* pr = in + base;
    const float* pg = pr + S;
    const float* pb = pg + S;

    float Ay[7][8];
    float Au[3][8];
    float Av[3][8];
#pragma unroll
    for (int k = 0; k < 7; ++k)
#pragma unroll
        for (int j = 0; j < 8; ++j) Ay[k][j] = 0.f;
#pragma unroll
    for (int k = 0; k < 3; ++k)
#pragma unroll
        for (int j = 0; j < 8; ++j) { Au[k][j] = 0.f; Av[k][j] = 0.f; }

    // ---- load + RGB2YUV + first DCT stage (A = D @ Xyuv), streamed by row ----
#pragma unroll
    for (int n = 0; n < 8; ++n) {
        float4 r0 = *(const float4*)(pr + n * W);
        float4 r1 = *(const float4*)(pr + n * W + 4);
        float4 g0 = *(const float4*)(pg + n * W);
        float4 g1 = *(const float4*)(pg + n * W + 4);
        float4 b0 = *(const float4*)(pb + n * W);
        float4 b1 = *(const float4*)(pb + n * W + 4);
        float rr[8] = {r0.x, r0.y, r0.z, r0.w, r1.x, r1.y, r1.z, r1.w};
        float gg[8] = {g0.x, g0.y, g0.z, g0.w, g1.x, g1.y, g1.z, g1.w};
        float bbv[8] = {b0.x, b0.y, b0.z, b0.w, b1.x, b1.y, b1.z, b1.w};
#pragma unroll
        for (int j = 0; j < 8; ++j) {
            float y =  0.299f   * rr[j] + 0.587f   * gg[j] + 0.114f   * bbv[j];
            float u = -0.14713f * rr[j] - 0.28886f * gg[j] + 0.436f   * bbv[j];
            float v =  0.615f   * rr[j] - 0.51499f * gg[j] - 0.10001f * bbv[j];
#pragma unroll
            for (int k = 0; k < 7; ++k) Ay[k][j] = fmaf(DCTL[k][n], y, Ay[k][j]);
#pragma unroll
            for (int k = 0; k < 3; ++k) Au[k][j] = fmaf(DCTL[k][n], u, Au[k][j]);
#pragma unroll
            for (int k = 0; k < 3; ++k) Av[k][j] = fmaf(DCTL[k][n], v, Av[k][j]);
        }
    }

    // ---- B = A @ D^T (kept prefix only), then C = B @ ID^T, in place over A ----
    // ID[j][l] = (l==0) ? 0.125 : 0.25*D[l][j]
#pragma unroll
    for (int k = 0; k < 7; ++k) {  // Y
        float Bk[8];
#pragma unroll
        for (int l = 0; l < 8; ++l) {
            if (l < CNTY[k]) {
                float s = 0.f;
#pragma unroll
                for (int j = 0; j < 8; ++j) s = fmaf(Ay[k][j], DCTL[l][j], s);
                Bk[l] = s;
            } else Bk[l] = 0.f;
        }
#pragma unroll
        for (int j = 0; j < 8; ++j) {
            float s = 0.f;
#pragma unroll
            for (int l = 0; l < 8; ++l) {
                if (l < CNTY[k]) {
                    float w = (l == 0) ? 0.125f : 0.25f * DCTL[l][j];
                    s = fmaf(Bk[l], w, s);
                }
            }
            Ay[k][j] = s;
        }
    }
#pragma unroll
    for (int k = 0; k < 3; ++k) {  // U
        float Bk[8];
#pragma unroll
        for (int l = 0; l < 8; ++l) {
            if (l < CNTC[k]) {
                float s = 0.f;
#pragma unroll
                for (int j = 0; j < 8; ++j) s = fmaf(Au[k][j], DCTL[l][j], s);
                Bk[l] = s;
            } else Bk[l] = 0.f;
        }
#pragma unroll
        for (int j = 0; j < 8; ++j) {
            float s = 0.f;
#pragma unroll
            for (int l = 0; l < 8; ++l) {
                if (l < CNTC[k]) {
                    float w = (l == 0) ? 0.125f : 0.25f * DCTL[l][j];
                    s = fmaf(Bk[l], w, s);
                }
            }
            Au[k][j] = s;
        }
    }
#pragma unroll
    for (int k = 0; k < 3; ++k) {  // V
        float Bk[8];
#pragma unroll
        for (int l = 0; l < 8; ++l) {
            if (l < CNTC[k]) {
                float s = 0.f;
#pragma unroll
                for (int j = 0; j < 8; ++j) s = fmaf(Av[k][j], DCTL[l][j], s);
                Bk[l] = s;
            } else Bk[l] = 0.f;
        }
#pragma unroll
        for (int j = 0; j < 8; ++j) {
            float s = 0.f;
#pragma unroll
            for (int l = 0; l < 8; ++l) {
                if (l < CNTC[k]) {
                    float w = (l == 0) ? 0.125f : 0.25f * DCTL[l][j];
                    s = fmaf(Bk[l], w, s);
                }
            }
            Av[k][j] = s;
        }
    }

    // ---- out = ID @ C, then YUV2RGB, stream stores by row ----
    // ID[n][k] = (k==0) ? 0.125 : 0.25*D[k][n]
    float* qr = out + base;
    float* qg = qr + S;
    float* qb = qg + S;
#pragma unroll
    for (int n = 0; n < 8; ++n) {
        float ro[8], go[8], bo[8];
#pragma unroll
        for (int j = 0; j < 8; ++j) {
            float y = 0.125f * Ay[0][j];
#pragma unroll
            for (int k = 1; k < 7; ++k) y = fmaf(0.25f * DCTL[k][n], Ay[k][j], y);
            float u = 0.125f * Au[0][j];
#pragma unroll
            for (int k = 1; k < 3; ++k) u = fmaf(0.25f * DCTL[k][n], Au[k][j], u);
            float v = 0.125f * Av[0][j];
#pragma unroll
            for (int k = 1; k < 3; ++k) v = fmaf(0.25f * DCTL[k][n], Av[k][j], v);
            ro[j] = fmaf(1.13983f, v, y);
            go[j] = fmaf(-0.5806f, v, fmaf(-0.39465f, u, y));
            bo[j] = fmaf(2.03211f, u, y);
        }
        *(float4*)(qr + n * W)     = make_float4(ro[0], ro[1], ro[2], ro[3]);
        *(float4*)(qr + n * W + 4) = make_float4(ro[4], ro[5], ro[6], ro[7]);
        *(float4*)(qg + n * W)     = make_float4(go[0], go[1], go[2], go[3]);
        *(float4*)(qg + n * W + 4) = make_float4(go[4], go[5], go[6], go[7]);
        *(float4*)(qb + n * W)     = make_float4(bo[0], bo[1], bo[2], bo[3]);
        *(float4*)(qb + n * W + 4) = make_float4(bo[4], bo[5], bo[6], bo[7]);
    }
}

extern "C" void kernel_launch(void* const* d_in, const int* in_sizes, int n_in,
                              void* d_out, int out_size)
{
    const float* in = (const float*)d_in[0];
    float* out = (float*)d_out;
    const int total = in_sizes[0];               // B*3*512*512
    const int B = total / (3 * 512 * 512);
    const int ntiles = B * 64 * 64;
    const int threads = 128;
    const int blocks = (ntiles + threads - 1) / threads;
    jpeg_fused_kernel<<<blocks, threads>>>(in, out, ntiles);
}

// round 2
// speedup vs baseline: 1.3249x; 1.3249x over previous
#include <cuda_runtime.h>

// cos(pi*t/16) constants
#define CC1 0.98078528040323044913f
#define CC2 0.92387953251128675613f
#define CC3 0.83146961230254523708f
#define CC4 0.70710678118654752440f
#define CC5 0.55557023301960222474f
#define CC6 0.38268343236508977173f
#define CC7 0.19509032201612826785f

// Two threads per 8x8 tile: thread owns 4 columns (half = g&1 -> cols half*4..half*4+3).
// Consecutive lanes -> consecutive 16B chunks -> fully coalesced 512B warp transactions.
// Horizontal transform couples the halves: one shfl_xor(1) + add per kept coefficient.
__global__ void __launch_bounds__(128)
jpeg_fused_kernel(const float* __restrict__ in, float* __restrict__ out, int nthr)
{
    const int g = blockIdx.x * blockDim.x + threadIdx.x;
    if (g >= nthr) return;
    const int tile = g >> 1;
    const int half = g & 1;

    // D[k][n] = cos(pi/8 * (n+0.5) * k)
    const float D[8][8] = {
        { 1.f,  1.f,  1.f,  1.f,  1.f,  1.f,  1.f,  1.f},
        { CC1,  CC3,  CC5,  CC7, -CC7, -CC5, -CC3, -CC1},
        { CC2,  CC6, -CC6, -CC2, -CC2, -CC6,  CC6,  CC2},
        { CC3, -CC7, -CC1, -CC5,  CC5,  CC1,  CC7, -CC3},
        { CC4, -CC4, -CC4,  CC4,  CC4, -CC4, -CC4,  CC4},
        { CC5, -CC1,  CC7,  CC3, -CC3, -CC7,  CC1, -CC5},
        { CC6, -CC2,  CC2, -CC6, -CC6,  CC2, -CC2,  CC6},
        { CC7, -CC5,  CC3, -CC1,  CC1, -CC3,  CC5, -CC7}
    };
    // zigzag keep masks are per-row prefixes:
    const int CNTY[7] = {6,5,4,4,3,2,1}; // Y: 25 coeffs, rows 0..6
    const int CNTC[3] = {4,3,2};         // U,V: 9 coeffs, rows 0..2

    // Column-half-dependent horizontal constants, materialized once (FSELs).
    // W[l][jj] = D[l][half*4 + jj].  l=0 row is 1.0 for both halves (folds away).
    float Wl[6][4];
#pragma unroll
    for (int l = 0; l < 6; ++l)
#pragma unroll
        for (int jj = 0; jj < 4; ++jj)
            Wl[l][jj] = half ? D[l][4 + jj] : D[l][jj];

    const int W = 512;
    const int S = 512 * 512;

    const int b  = tile >> 12;       // tiles per image = 64*64
    const int t  = tile & 4095;
    const int ty = t >> 6;
    const int tx = t & 63;

    const size_t base = (size_t)b * (3 * S) + (size_t)(ty * 8) * W
                      + (size_t)(tx * 8) + (size_t)(half * 4);
    const float* pr = in + base;
    const float* pg = pr + S;
    const float* pb = pg + S;

    float Ay[7][4];
    float Au[3][4];
    float Av[3][4];
#pragma unroll
    for (int k = 0; k < 7; ++k)
#pragma unroll
        for (int jj = 0; jj < 4; ++jj) Ay[k][jj] = 0.f;
#pragma unroll
    for (int k = 0; k < 3; ++k)
#pragma unroll
        for (int jj = 0; jj < 4; ++jj) { Au[k][jj] = 0.f; Av[k][jj] = 0.f; }

    // ---- load + RGB2YUV + vertical DCT (A = D @ Xyuv), this thread's 4 cols ----
#pragma unroll
    for (int n = 0; n < 8; ++n) {
        float4 R = *(const float4*)(pr + n * W);
        float4 G = *(const float4*)(pg + n * W);
        float4 Bc = *(const float4*)(pb + n * W);
        float rr[4] = {R.x, R.y, R.z, R.w};
        float gg[4] = {G.x, G.y, G.z, G.w};
        float bb[4] = {Bc.x, Bc.y, Bc.z, Bc.w};
#pragma unroll
        for (int jj = 0; jj < 4; ++jj) {
            float y =  0.299f   * rr[jj] + 0.587f   * gg[jj] + 0.114f   * bb[jj];
            float u = -0.14713f * rr[jj] - 0.28886f * gg[jj] + 0.436f   * bb[jj];
            float v =  0.615f   * rr[jj] - 0.51499f * gg[jj] - 0.10001f * bb[jj];
#pragma unroll
            for (int k = 0; k < 7; ++k) Ay[k][jj] = fmaf(D[k][n], y, Ay[k][jj]);
#pragma unroll
            for (int k = 0; k < 3; ++k) Au[k][jj] = fmaf(D[k][n], u, Au[k][jj]);
#pragma unroll
            for (int k = 0; k < 3; ++k) Av[k][jj] = fmaf(D[k][n], v, Av[k][jj]);
        }
    }

    // ---- horizontal DCT (kept prefix), then horizontal inverse, in place ----
    // B[k][l] = sum_j A[k][j] D[l][j]  (partial over own 4 cols + partner via shfl)
    // Stored back: A[k][jj] := 4 * (0.125*B[0] + sum_{l>=1} 0.25*W[l][jj]*B[l])
    //            =  0.5*B[0] + sum_{l>=1} W[l][jj]*B[l]
    // (the factor 1/4 is folded into the stage-3 vertical immediates)

#pragma unroll
    for (int k = 0; k < 7; ++k) {  // Y
        float Bv[6];
        const int c = CNTY[k];
#pragma unroll
        for (int l = 0; l < 6; ++l) {
            if (l < c) {
                float p = Ay[k][0] * Wl[l][0];
                p = fmaf(Ay[k][1], Wl[l][1], p);
                p = fmaf(Ay[k][2], Wl[l][2], p);
                p = fmaf(Ay[k][3], Wl[l][3], p);
                p += __shfl_xor_sync(0xffffffffu, p, 1);
                Bv[l] = p;
            }
        }
        const float b0 = 0.5f * Bv[0];
#pragma unroll
        for (int jj = 0; jj < 4; ++jj) {
            float s = b0;
#pragma unroll
            for (int l = 1; l < 6; ++l)
                if (l < c) s = fmaf(Bv[l], Wl[l][jj], s);
            Ay[k][jj] = s;
        }
    }
#pragma unroll
    for (int k = 0; k < 3; ++k) {  // U
        float Bv[4];
        const int c = CNTC[k];
#pragma unroll
        for (int l = 0; l < 4; ++l) {
            if (l < c) {
                float p = Au[k][0] * Wl[l][0];
                p = fmaf(Au[k][1], Wl[l][1], p);
                p = fmaf(Au[k][2], Wl[l][2], p);
                p = fmaf(Au[k][3], Wl[l][3], p);
                p += __shfl_xor_sync(0xffffffffu, p, 1);
                Bv[l] = p;
            }
        }
        const float b0 = 0.5f * Bv[0];
#pragma unroll
        for (int jj = 0; jj < 4; ++jj) {
            float s = b0;
#pragma unroll
            for (int l = 1; l < 4; ++l)
                if (l < c) s = fmaf(Bv[l], Wl[l][jj], s);
            Au[k][jj] = s;
        }
    }
#pragma unroll
    for (int k = 0; k < 3; ++k) {  // V
        float Bv[4];
        const int c = CNTC[k];
#pragma unroll
        for (int l = 0; l < 4; ++l) {
            if (l < c) {
                float p = Av[k][0] * Wl[l][0];
                p = fmaf(Av[k][1], Wl[l][1], p);
                p = fmaf(Av[k][2], Wl[l][2], p);
                p = fmaf(Av[k][3], Wl[l][3], p);
                p += __shfl_xor_sync(0xffffffffu, p, 1);
                Bv[l] = p;
            }
        }
        const float b0 = 0.5f * Bv[0];
#pragma unroll
        for (int jj = 0; jj < 4; ++jj) {
            float s = b0;
#pragma unroll
            for (int l = 1; l < 4; ++l)
                if (l < c) s = fmaf(Bv[l], Wl[l][jj], s);
            Av[k][jj] = s;
        }
    }

    // ---- vertical inverse (extra 1/4 folded: ID'[n][k] = k==0 ? 0.03125 : 0.0625*D[k][n])
    //      + YUV2RGB + coalesced stores ----
    float* qr = out + base;
    float* qg = qr + S;
    float* qb = qg + S;
#pragma unroll
    for (int n = 0; n < 8; ++n) {
        float ro[4], go[4], bo[4];
#pragma unroll
        for (int jj = 0; jj < 4; ++jj) {
            float y = 0.03125f * Ay[0][jj];
#pragma unroll
            for (int k = 1; k < 7; ++k) y = fmaf(0.0625f * D[k][n], Ay[k][jj], y);
            float u = 0.03125f * Au[0][jj];
#pragma unroll
            for (int k = 1; k < 3; ++k) u = fmaf(0.0625f * D[k][n], Au[k][jj], u);
            float v = 0.03125f * Av[0][jj];
#pragma unroll
            for (int k = 1; k < 3; ++k) v = fmaf(0.0625f * D[k][n], Av[k][jj], v);
            ro[jj] = fmaf(1.13983f, v, y);
            go[jj] = fmaf(-0.5806f, v, fmaf(-0.39465f, u, y));
            bo[jj] = fmaf(2.03211f, u, y);
        }
        *(float4*)(qr + n * W) = make_float4(ro[0], ro[1], ro[2], ro[3]);
        *(float4*)(qg + n * W) = make_float4(go[0], go[1], go[2], go[3]);
        *(float4*)(qb + n * W) = make_float4(bo[0], bo[1], bo[2], bo[3]);
    }
}

extern "C" void kernel_launch(void* const* d_in, const int* in_sizes, int n_in,
                              void* d_out, int out_size)
{
    const float* in = (const float*)d_in[0];
    float* out = (float*)d_out;
    const int total = in_sizes[0];               // B*3*512*512
    const int B = total / (3 * 512 * 512);
    const int nthr = B * 64 * 64 * 2;            // 2 threads per tile
    const int threads = 128;
    const int blocks = (nthr + threads - 1) / threads;
    jpeg_fused_kernel<<<blocks, threads>>>(in, out, nthr);
}